// round 5
// baseline (speedup 1.0000x reference)
#include <cuda_runtime.h>
#include <cstdint>

// Residual quantizer, fp32, arithmetic mirror of the reference
// (validated rel_err 7.351969e-4; all FMA chains bitwise-preserved).
// Round 5:
//  * codebook transposed once by a prep kernel into __device__ global
//    cbT[lvl][dim][code] (+ precomputed |c|^2) -> main kernel reads codes
//    with warp-uniform LDG.128 (1 request/warp, L2-resident), freeing the
//    LDS port and removing C from shared memory.
//  * residual is thread-private in smem (point-major slots, stride 132
//    floats -> conflict-free float4 access): no __syncthreads in the main
//    loop, smem 67.6 KB/block -> 3 blocks x 128 thr = 12 warps/SM.
//  * 2 points/thread, 16-code tiles: per 4 dims = 2 LDS + 16 LDG + 64 FMA2.

#define KCODES 256
#define DIM 64
#define LEVELS 4
#define TPB 128
#define PPT 2
#define NPTS (TPB * PPT)          // 256 points per block
#define SLOT 132                  // floats per thread slot (528 B, 16*odd)
#define SMEM_BYTES (TPB * SLOT * 4)   // 67584

__device__ float g_cbT[LEVELS * DIM * KCODES];   // [lvl][dim][code]
__device__ float g_c2[LEVELS * KCODES];

#define FMA2(d, a, b, c) \
    asm("fma.rn.f32x2 %0, %1, %2, %3;" : "=l"(d) : "l"(a), "l"(b), "l"(c))
#define DUP2(d, s) asm("mov.b64 %0, {%1, %1};" : "=l"(d) : "f"(s))

// ---- prep: transpose codebook + per-code squared norms (runs once) ----
__global__ void prep_kernel(const float* __restrict__ cb) {
    const int lvl = blockIdx.x;
    const int k = threadIdx.x;
    const float4* src = reinterpret_cast<const float4*>(
        cb + ((size_t)lvl * KCODES + k) * DIM);
    float v[DIM];
#pragma unroll
    for (int i = 0; i < 16; i++) {
        float4 t = src[i];
        v[4 * i + 0] = t.x; v[4 * i + 1] = t.y;
        v[4 * i + 2] = t.z; v[4 * i + 3] = t.w;
    }
    float s = 0.f;
#pragma unroll
    for (int j = 0; j < DIM; j++)
        s = __fadd_rn(s, __fmul_rn(v[j], v[j]));   // reference order
    g_c2[lvl * KCODES + k] = s;
#pragma unroll
    for (int j = 0; j < DIM; j++)
        g_cbT[(lvl * DIM + j) * KCODES + k] = v[j];   // coalesced in k
}

__global__ void __launch_bounds__(TPB, 3)
rq_kernel(const float* __restrict__ z, const float* __restrict__ cb,
          float* __restrict__ out, int B) {
    extern __shared__ __align__(16) float smem[];
    const int tid = threadIdx.x;
    float* Rs = smem + tid * SLOT;            // thread-private slot
    float4* R4 = reinterpret_cast<float4*>(Rs);   // [0..15]=pt0, [16..31]=pt1

    const long p0_raw = (long)blockIdx.x * NPTS + 2 * tid;
    const long p0 = p0_raw < B ? p0_raw : (B - 1);
    const long p1 = (p0_raw + 1) < B ? (p0_raw + 1) : (B - 1);

    // ---- init residual from z ----
    {
        const float4* z0 = reinterpret_cast<const float4*>(z + p0 * DIM);
        const float4* z1 = reinterpret_cast<const float4*>(z + p1 * DIM);
#pragma unroll
        for (int i = 0; i < 16; i++) { R4[i] = z0[i]; R4[16 + i] = z1[i]; }
    }

    int id0[LEVELS], id1[LEVELS];

#pragma unroll 1
    for (int lvl = 0; lvl < LEVELS; lvl++) {
        const float* cbL = g_cbT + (size_t)lvl * DIM * KCODES;
        const float* c2L = g_c2 + lvl * KCODES;

        // ---- r2: sequential square-then-add over dims, per point ----
        float r2a = 0.f, r2b = 0.f;
#pragma unroll
        for (int i = 0; i < 16; i++) {
            float4 a = R4[i], b = R4[16 + i];
            r2a = __fadd_rn(r2a, __fmul_rn(a.x, a.x));
            r2a = __fadd_rn(r2a, __fmul_rn(a.y, a.y));
            r2a = __fadd_rn(r2a, __fmul_rn(a.z, a.z));
            r2a = __fadd_rn(r2a, __fmul_rn(a.w, a.w));
            r2b = __fadd_rn(r2b, __fmul_rn(b.x, b.x));
            r2b = __fadd_rn(r2b, __fmul_rn(b.y, b.y));
            r2b = __fadd_rn(r2b, __fmul_rn(b.z, b.z));
            r2b = __fadd_rn(r2b, __fmul_rn(b.w, b.w));
        }

        float best0 = __int_as_float(0x7F800000);
        float best1 = __int_as_float(0x7F800000);
        int bi0 = 0, bi1 = 0;

        // ---- distance pass: 16 tiles x 16 codes, uniform LDG.128 codes ----
#pragma unroll 1
        for (int kt = 0; kt < 16; kt++) {
            const ulonglong2* cbp =
                reinterpret_cast<const ulonglong2*>(cbL) + kt * 4;
            unsigned long long a0[8], a1[8];
#pragma unroll
            for (int m = 0; m < 8; m++) { a0[m] = 0ULL; a1[m] = 0ULL; }

#pragma unroll
            for (int jg = 0; jg < 16; jg++) {
                float4 ra4 = R4[jg];
                float4 rb4 = R4[16 + jg];
                float ra_[4] = {ra4.x, ra4.y, ra4.z, ra4.w};
                float rb_[4] = {rb4.x, rb4.y, rb4.z, rb4.w};
#pragma unroll
                for (int u = 0; u < 4; u++) {
                    const int j = 4 * jg + u;
                    unsigned long long ra, rb;
                    DUP2(ra, ra_[u]); DUP2(rb, rb_[u]);
                    ulonglong2 v0 = __ldg(cbp + (size_t)j * 64 + 0);
                    ulonglong2 v1 = __ldg(cbp + (size_t)j * 64 + 1);
                    ulonglong2 v2 = __ldg(cbp + (size_t)j * 64 + 2);
                    ulonglong2 v3 = __ldg(cbp + (size_t)j * 64 + 3);
                    unsigned long long c[8] = {v0.x, v0.y, v1.x, v1.y,
                                               v2.x, v2.y, v3.x, v3.y};
#pragma unroll
                    for (int m = 0; m < 8; m++) FMA2(a0[m], ra, c[m], a0[m]);
#pragma unroll
                    for (int m = 0; m < 8; m++) FMA2(a1[m], rb, c[m], a1[m]);
                }
            }
            // ---- distances + argmin (ascending k, strict <) ----
#pragma unroll
            for (int m = 0; m < 8; m++) {
                const int k0 = kt * 16 + 2 * m;
                const float cc0 = __ldg(c2L + k0);
                const float cc1 = __ldg(c2L + k0 + 1);
                float lo, hi;
                asm("mov.b64 {%0,%1}, %2;" : "=f"(lo), "=f"(hi) : "l"(a0[m]));
                float d0 = __fadd_rn(__fsub_rn(r2a, __fmul_rn(2.0f, lo)), cc0);
                float d1 = __fadd_rn(__fsub_rn(r2a, __fmul_rn(2.0f, hi)), cc1);
                if (d0 < best0) { best0 = d0; bi0 = k0; }
                if (d1 < best0) { best0 = d1; bi0 = k0 + 1; }
                asm("mov.b64 {%0,%1}, %2;" : "=f"(lo), "=f"(hi) : "l"(a1[m]));
                float e0 = __fadd_rn(__fsub_rn(r2b, __fmul_rn(2.0f, lo)), cc0);
                float e1 = __fadd_rn(__fsub_rn(r2b, __fmul_rn(2.0f, hi)), cc1);
                if (e0 < best1) { best1 = e0; bi1 = k0; }
                if (e1 < best1) { best1 = e1; bi1 = k0 + 1; }
            }
        }
        id0[lvl] = bi0; id1[lvl] = bi1;

        // ---- residual -= chosen codes (K-major gather, L2 hits) ----
        {
            const float4* c0 = reinterpret_cast<const float4*>(
                cb + ((size_t)lvl * KCODES + bi0) * DIM);
            const float4* c1 = reinterpret_cast<const float4*>(
                cb + ((size_t)lvl * KCODES + bi1) * DIM);
#pragma unroll
            for (int i = 0; i < 16; i++) {
                float4 a = R4[i], ca = __ldg(c0 + i);
                a.x = __fsub_rn(a.x, ca.x); a.y = __fsub_rn(a.y, ca.y);
                a.z = __fsub_rn(a.z, ca.z); a.w = __fsub_rn(a.w, ca.w);
                R4[i] = a;
                float4 b = R4[16 + i], cbv = __ldg(c1 + i);
                b.x = __fsub_rn(b.x, cbv.x); b.y = __fsub_rn(b.y, cbv.y);
                b.z = __fsub_rn(b.z, cbv.z); b.w = __fsub_rn(b.w, cbv.w);
                R4[16 + i] = b;
            }
        }
    }

    // ---- epilogue: quantized = ((q0+q1)+q2)+q3 from gmem gathers ----
    const long pts[2] = {p0, p1};
    const int* ids[2] = {id0, id1};
    const bool valid[2] = {p0_raw < B, (p0_raw + 1) < B};
#pragma unroll 1
    for (int s = 0; s < 2; s++) {
        if (!valid[s]) continue;
        const long p = pts[s];
        float q[DIM];
#pragma unroll
        for (int j = 0; j < DIM; j++) q[j] = 0.f;
#pragma unroll 1
        for (int lvl = 0; lvl < LEVELS; lvl++) {
            const float4* cp = reinterpret_cast<const float4*>(
                cb + ((size_t)lvl * KCODES + ids[s][lvl]) * DIM);
#pragma unroll
            for (int i = 0; i < 16; i++) {
                float4 v = __ldg(cp + i);
                q[4 * i + 0] = __fadd_rn(q[4 * i + 0], v.x);
                q[4 * i + 1] = __fadd_rn(q[4 * i + 1], v.y);
                q[4 * i + 2] = __fadd_rn(q[4 * i + 2], v.z);
                q[4 * i + 3] = __fadd_rn(q[4 * i + 3], v.w);
            }
        }
        const float4* zp = reinterpret_cast<const float4*>(z + p * DIM);
        float4* qst = reinterpret_cast<float4*>(out + (size_t)p * DIM);
        float4* qq  = reinterpret_cast<float4*>(out + (size_t)B * (DIM + 4) +
                                                (size_t)p * DIM);
#pragma unroll
        for (int i = 0; i < 16; i++) {
            float4 zv = zp[i];
            float4 qv = make_float4(q[4 * i + 0], q[4 * i + 1],
                                    q[4 * i + 2], q[4 * i + 3]);
            float4 sv;
            sv.x = __fadd_rn(zv.x, __fsub_rn(qv.x, zv.x));
            sv.y = __fadd_rn(zv.y, __fsub_rn(qv.y, zv.y));
            sv.z = __fadd_rn(zv.z, __fsub_rn(qv.z, zv.z));
            sv.w = __fadd_rn(zv.w, __fsub_rn(qv.w, zv.w));
            qst[i] = sv;
            qq[i] = qv;
        }
        float4 iv;
        iv.x = (float)ids[s][0]; iv.y = (float)ids[s][1];
        iv.z = (float)ids[s][2]; iv.w = (float)ids[s][3];
        reinterpret_cast<float4*>(out + (size_t)B * DIM)[p] = iv;
    }
}

extern "C" void kernel_launch(void* const* d_in, const int* in_sizes, int n_in,
                              void* d_out, int out_size) {
    const float* z = (const float*)d_in[0];
    const float* cb = (const float*)d_in[1];
    float* out = (float*)d_out;
    int B = in_sizes[0] / DIM;

    prep_kernel<<<LEVELS, KCODES>>>(cb);

    cudaFuncSetAttribute(rq_kernel, cudaFuncAttributeMaxDynamicSharedMemorySize,
                         SMEM_BYTES);
    int blocks = (B + NPTS - 1) / NPTS;
    rq_kernel<<<blocks, TPB, SMEM_BYTES>>>(z, cb, out, B);
}

// round 6
// speedup vs baseline: 1.5329x; 1.5329x over previous
#include <cuda_runtime.h>
#include <cstdint>

// Residual quantizer, fp32, arithmetic mirror of the reference
// (validated rel_err 7.351969e-4, all FMA chains bitwise-preserved).
// Round 6 = round 4 structure (best, 3374us) + issue-efficiency work:
//  * 32-code tiles (8 tiles instead of 16): residual LDS/DUP traffic halved,
//    32 independent acc chains per thread (double the ILP to hide LDS lat).
//  * chunk-wise epilogue (no q[64] array) -> much lower reg high-water mark,
//    giving ptxas room to hoist code/residual loads across j iterations.
//  * codebook broadcasts from smem (round 5 showed LDG is worse than LDS).

#define KCODES 256
#define DIM 64
#define LEVELS 4
#define TPB 256
#define NPTS 512                 // 2 points per thread
#define RST 512                  // R row stride (floats)
#define CST 260                  // C row stride (floats), 1040 B rows
#define R_BYTES (DIM * RST * 4)              // 131072
#define C_BYTES (DIM * CST * 4)              // 66560
#define SMEM_BYTES (R_BYTES + C_BYTES + KCODES * 4)   // 198656

#define FMA2(d, a, b, c) \
    asm("fma.rn.f32x2 %0, %1, %2, %3;" : "=l"(d) : "l"(a), "l"(b), "l"(c))
#define DUP2(d, s) asm("mov.b64 %0, {%1, %1};" : "=l"(d) : "f"(s))
#define LDS_V2U64(a, b, addr) \
    asm("ld.shared.v2.u64 {%0,%1}, [%2];" : "=l"(a), "=l"(b) : "r"(addr))

__global__ void __launch_bounds__(256, 1)
rq_kernel(const float* __restrict__ z, const float* __restrict__ cb,
          float* __restrict__ out, int B) {
    extern __shared__ __align__(16) char sm_raw[];
    float* R  = reinterpret_cast<float*>(sm_raw);
    float* C  = reinterpret_cast<float*>(sm_raw + R_BYTES);
    float* c2 = reinterpret_cast<float*>(sm_raw + R_BYTES + C_BYTES);

    const int tid = threadIdx.x;
    const int lp0 = 2 * tid;
    const long p0_raw = (long)blockIdx.x * NPTS + lp0;
    const long p0 = p0_raw < B ? p0_raw : (B - 1);
    const long p1 = (p0_raw + 1) < B ? (p0_raw + 1) : (B - 1);

    // ---- init residual R[j][lp0..lp0+1] = z ----
    {
        const float4* z0 = reinterpret_cast<const float4*>(z + p0 * DIM);
        const float4* z1 = reinterpret_cast<const float4*>(z + p1 * DIM);
#pragma unroll
        for (int i = 0; i < 16; i++) {
            float4 a = z0[i], b = z1[i];
            *reinterpret_cast<float2*>(R + (4 * i + 0) * RST + lp0) =
                make_float2(a.x, b.x);
            *reinterpret_cast<float2*>(R + (4 * i + 1) * RST + lp0) =
                make_float2(a.y, b.y);
            *reinterpret_cast<float2*>(R + (4 * i + 2) * RST + lp0) =
                make_float2(a.z, b.z);
            *reinterpret_cast<float2*>(R + (4 * i + 3) * RST + lp0) =
                make_float2(a.w, b.w);
        }
    }

    const unsigned smR = (unsigned)__cvta_generic_to_shared(R) + lp0 * 4;
    const unsigned smC = (unsigned)__cvta_generic_to_shared(C);

    int id0[LEVELS], id1[LEVELS];

#pragma unroll 1
    for (int lvl = 0; lvl < LEVELS; lvl++) {
        __syncthreads();   // prev level's residual update read C
        // ---- stage codebook level transposed: C[j][tid] = cb[lvl][tid][j]
        {
            const float4* src = reinterpret_cast<const float4*>(
                cb + ((size_t)lvl * KCODES + tid) * DIM);
#pragma unroll
            for (int i = 0; i < 16; i++) {
                float4 v = src[i];
                C[(4 * i + 0) * CST + tid] = v.x;
                C[(4 * i + 1) * CST + tid] = v.y;
                C[(4 * i + 2) * CST + tid] = v.z;
                C[(4 * i + 3) * CST + tid] = v.w;
            }
        }
        __syncthreads();
        // ---- c2[k]: square-then-add, sequential over dims ----
        {
            float s = 0.f;
#pragma unroll
            for (int j = 0; j < DIM; j++) {
                float c = C[j * CST + tid];
                s = __fadd_rn(s, __fmul_rn(c, c));
            }
            c2[tid] = s;
        }
        __syncthreads();

        // ---- r2 for my 2 points (sequential chains) ----
        float r2a = 0.f, r2b = 0.f;
#pragma unroll
        for (int j = 0; j < DIM; j++) {
            float2 rv = *reinterpret_cast<const float2*>(R + j * RST + lp0);
            r2a = __fadd_rn(r2a, __fmul_rn(rv.x, rv.x));
            r2b = __fadd_rn(r2b, __fmul_rn(rv.y, rv.y));
        }

        float best0 = __int_as_float(0x7F800000);
        float best1 = __int_as_float(0x7F800000);
        int bi0 = 0, bi1 = 0;

        // ---- distance pass: 8 tiles of 32 codes, warp-uniform code loads
#pragma unroll 1
        for (int kt = 0; kt < 8; kt++) {
            const unsigned cA = smC + kt * 128;   // 32 codes * 4 B
            unsigned long long a0[16], a1[16];
#pragma unroll
            for (int m = 0; m < 16; m++) { a0[m] = 0ULL; a1[m] = 0ULL; }

#pragma unroll 8
            for (int j = 0; j < DIM; j++) {
                float rx, ry;
                asm("ld.shared.v2.f32 {%0,%1}, [%2];"
                    : "=f"(rx), "=f"(ry) : "r"(smR + j * (RST * 4)));
                unsigned long long ra, rb;
                DUP2(ra, rx); DUP2(rb, ry);
                unsigned long long c[16];
                const unsigned ca = cA + j * (CST * 4);
                LDS_V2U64(c[0],  c[1],  ca);
                LDS_V2U64(c[2],  c[3],  ca + 16);
                LDS_V2U64(c[4],  c[5],  ca + 32);
                LDS_V2U64(c[6],  c[7],  ca + 48);
                LDS_V2U64(c[8],  c[9],  ca + 64);
                LDS_V2U64(c[10], c[11], ca + 80);
                LDS_V2U64(c[12], c[13], ca + 96);
                LDS_V2U64(c[14], c[15], ca + 112);
#pragma unroll
                for (int m = 0; m < 16; m++) FMA2(a0[m], ra, c[m], a0[m]);
#pragma unroll
                for (int m = 0; m < 16; m++) FMA2(a1[m], rb, c[m], a1[m]);
            }
            // ---- distances + argmin (ascending k, strict < => first-min)
#pragma unroll
            for (int m = 0; m < 16; m++) {
                const int k0 = kt * 32 + 2 * m;
                const float cc0 = c2[k0], cc1 = c2[k0 + 1];
                float lo, hi;
                asm("mov.b64 {%0,%1}, %2;" : "=f"(lo), "=f"(hi) : "l"(a0[m]));
                float d0 = __fadd_rn(__fsub_rn(r2a, __fmul_rn(2.0f, lo)), cc0);
                float d1 = __fadd_rn(__fsub_rn(r2a, __fmul_rn(2.0f, hi)), cc1);
                if (d0 < best0) { best0 = d0; bi0 = k0; }
                if (d1 < best0) { best0 = d1; bi0 = k0 + 1; }
                asm("mov.b64 {%0,%1}, %2;" : "=f"(lo), "=f"(hi) : "l"(a1[m]));
                float e0 = __fadd_rn(__fsub_rn(r2b, __fmul_rn(2.0f, lo)), cc0);
                float e1 = __fadd_rn(__fsub_rn(r2b, __fmul_rn(2.0f, hi)), cc1);
                if (e0 < best1) { best1 = e0; bi1 = k0; }
                if (e1 < best1) { best1 = e1; bi1 = k0 + 1; }
            }
        }
        id0[lvl] = bi0; id1[lvl] = bi1;

        // ---- residual update for my own points (reads C; sync at loop top)
#pragma unroll
        for (int j = 0; j < DIM; j++) {
            float2 rv = *reinterpret_cast<const float2*>(R + j * RST + lp0);
            rv.x = __fsub_rn(rv.x, C[j * CST + bi0]);
            rv.y = __fsub_rn(rv.y, C[j * CST + bi1]);
            *reinterpret_cast<float2*>(R + j * RST + lp0) = rv;
        }
    }

    // ---- epilogue (chunk-wise, low reg pressure) ----
    const long pts[2] = {p0, p1};
    const bool valid[2] = {p0_raw < B, (p0_raw + 1) < B};
#pragma unroll 1
    for (int s = 0; s < 2; s++) {
        if (!valid[s]) continue;
        const long p = pts[s];
        const int* ids = (s == 0) ? id0 : id1;
        const float4* cp0 = reinterpret_cast<const float4*>(
            cb + ((size_t)0 * KCODES + ids[0]) * DIM);
        const float4* cp1 = reinterpret_cast<const float4*>(
            cb + ((size_t)1 * KCODES + ids[1]) * DIM);
        const float4* cp2 = reinterpret_cast<const float4*>(
            cb + ((size_t)2 * KCODES + ids[2]) * DIM);
        const float4* cp3 = reinterpret_cast<const float4*>(
            cb + ((size_t)3 * KCODES + ids[3]) * DIM);
        const float4* zp = reinterpret_cast<const float4*>(z + p * DIM);
        float4* qst = reinterpret_cast<float4*>(out + (size_t)p * DIM);
        float4* qq  = reinterpret_cast<float4*>(out + (size_t)B * (DIM + 4) +
                                                (size_t)p * DIM);
#pragma unroll
        for (int i = 0; i < 16; i++) {
            float4 v0 = __ldg(cp0 + i), v1 = __ldg(cp1 + i);
            float4 v2 = __ldg(cp2 + i), v3 = __ldg(cp3 + i);
            // quantized = ((q0 + q1) + q2) + q3, sequential (matches ref)
            float4 qv;
            qv.x = __fadd_rn(__fadd_rn(__fadd_rn(v0.x, v1.x), v2.x), v3.x);
            qv.y = __fadd_rn(__fadd_rn(__fadd_rn(v0.y, v1.y), v2.y), v3.y);
            qv.z = __fadd_rn(__fadd_rn(__fadd_rn(v0.z, v1.z), v2.z), v3.z);
            qv.w = __fadd_rn(__fadd_rn(__fadd_rn(v0.w, v1.w), v2.w), v3.w);
            float4 zv = zp[i];
            float4 sv;
            sv.x = __fadd_rn(zv.x, __fsub_rn(qv.x, zv.x));
            sv.y = __fadd_rn(zv.y, __fsub_rn(qv.y, zv.y));
            sv.z = __fadd_rn(zv.z, __fsub_rn(qv.z, zv.z));
            sv.w = __fadd_rn(zv.w, __fsub_rn(qv.w, zv.w));
            qst[i] = sv;
            qq[i] = qv;
        }
        float4 iv;
        iv.x = (float)ids[0]; iv.y = (float)ids[1];
        iv.z = (float)ids[2]; iv.w = (float)ids[3];
        reinterpret_cast<float4*>(out + (size_t)B * DIM)[p] = iv;
    }
}

extern "C" void kernel_launch(void* const* d_in, const int* in_sizes, int n_in,
                              void* d_out, int out_size) {
    const float* z = (const float*)d_in[0];
    const float* cb = (const float*)d_in[1];
    float* out = (float*)d_out;
    int B = in_sizes[0] / DIM;

    cudaFuncSetAttribute(rq_kernel, cudaFuncAttributeMaxDynamicSharedMemorySize,
                         SMEM_BYTES);
    int blocks = (B + NPTS - 1) / NPTS;
    rq_kernel<<<blocks, TPB, SMEM_BYTES>>>(z, cb, out, B);
}